// round 7
// baseline (speedup 1.0000x reference)
#include <cuda_runtime.h>
#include <cuda_bf16.h>

#define BEV_H 512
#define BEV_W 512
#define BEV_C 64
#define HW (BEV_H * BEV_W)   // 262144 = 2^18

// Scratch: last-writer pillar index per BEV cell (up to 8 batches).
__device__ int g_last[8 * HW];
// Zero row for empty cells (zero-initialized, never written).
__device__ __align__(16) float g_zero[BEV_C];

// ---------------------------------------------------------------------------
// Scatter: last-occurrence-wins via atomicMax on pillar index.
// ---------------------------------------------------------------------------
__global__ void bev_scatter_kernel(const int* __restrict__ coords, int P) {
    int t = blockIdx.x * blockDim.x + threadIdx.x;
    int p0 = t * 4;
    if (p0 + 3 < P) {
        const int4* c4 = reinterpret_cast<const int4*>(coords + p0 * 3);
        int4 a  = __ldg(c4 + 0);  // b0 r0 c0 b1
        int4 bb = __ldg(c4 + 1);  // r1 c1 b2 r2
        int4 cc = __ldg(c4 + 2);  // c2 b3 r3 c3
        int bs[4] = {a.x, a.w, bb.z, cc.y};
        int rs[4] = {a.y, bb.x, bb.w, cc.z};
        int cs[4] = {a.z, bb.y, cc.x, cc.w};
#pragma unroll
        for (int k = 0; k < 4; k++) {
            int r = min(max(rs[k], 0), BEV_H - 1);
            int c = min(max(cs[k], 0), BEV_W - 1);
            atomicMax(&g_last[bs[k] * HW + r * BEV_W + c], p0 + k);
        }
    } else if (p0 < P) {
        for (int p = p0; p < P; p++) {
            int b = coords[3 * p + 0];
            int r = min(max(coords[3 * p + 1], 0), BEV_H - 1);
            int c = min(max(coords[3 * p + 2], 0), BEV_W - 1);
            atomicMax(&g_last[b * HW + r * BEV_W + c], p);
        }
    }
}

// ---------------------------------------------------------------------------
// Gather + transpose. Warp-autonomous: each warp owns 32 consecutive cells and
// a private 4KB smem slice; only __syncwarp (no CTA barriers -> no phase lock).
// Two halves of 32 channels each:
//   Produce: 4-lane team per row, 4 row-batches (s): lane q loads float4
//            (8h+q) and (8h+q+4) of row(8s+cw); STS.32 into swizzled tile
//            word(ch,cell) = ch*32 + (cell ^ 8q)  -> banks cw+8(s^q), 32
//            distinct per instruction (conflict-free).
//   Consume: instr k: lane l (d=l>>3, c8=l&7) LDS.128 cells c8*4..+3 of
//            channel 4k+d at word 4k*32+d*32 + ((c8*4) ^ (8*(k&3))), then
//            STG.128 -> each instruction = 4 channels x one FULL 128B line
//            (warp covers all 32 cells of each channel): 2 wf/cell stores.
// ---------------------------------------------------------------------------
__global__ void __launch_bounds__(256) bev_gather_kernel(
    const float* __restrict__ feats,
    float* __restrict__ out) {
    __shared__ float sbuf[8][32 * 32];   // 4KB per warp, 32KB per CTA

    const int widx = threadIdx.x >> 5;
    const int l    = threadIdx.x & 31;
    const int q  = l & 3;     // producer: lane quarter in 4-lane row team
    const int cw = l >> 2;    // producer: 0..7 row-within-batch
    const int d  = l >> 3;    // consumer: channel sub-index 0..3
    const int c8 = l & 7;     // consumer: cell-quad index 0..7

    const int wgid = blockIdx.x * 8 + widx;
    const int base = wgid * 32;              // first cell (32-aligned, in-batch)
    const int b    = base >> 18;
    const int pos  = base & (HW - 1);

    // One coalesced g_last load per lane; rows distributed via shuffle.
    const int myLast = __ldg(&g_last[base + l]);
    const float4* rows[4];
#pragma unroll
    for (int s = 0; s < 4; s++) {
        int lc = __shfl_sync(0xffffffffu, myLast, 8 * s + cw);
        rows[s] = reinterpret_cast<const float4*>(
            lc >= 0 ? feats + (size_t)lc * BEV_C : g_zero);
    }

    float* buf  = sbuf[widx];
    float* outb = out + (size_t)b * (BEV_C * HW) + pos;

#pragma unroll
    for (int h = 0; h < 2; h++) {
        // ---- produce: 8 LDG.128 up front (MLP), then 32 swizzled STS.32 ----
        float4 A[4], B[4];
#pragma unroll
        for (int s = 0; s < 4; s++) {
            A[s] = __ldg(rows[s] + 8 * h + q);      // channels 32h+4q+e
            B[s] = __ldg(rows[s] + 8 * h + q + 4);  // channels 32h+16+4q+e
        }
#pragma unroll
        for (int s = 0; s < 4; s++) {
            const int cs = cw + 8 * (s ^ q);        // swizzled cell slot
            float* pA = buf + (4 * q) * 32 + cs;
            pA[0 * 32] = A[s].x; pA[1 * 32] = A[s].y;
            pA[2 * 32] = A[s].z; pA[3 * 32] = A[s].w;
            float* pB = buf + (16 + 4 * q) * 32 + cs;
            pB[0 * 32] = B[s].x; pB[1 * 32] = B[s].y;
            pB[2 * 32] = B[s].z; pB[3 * 32] = B[s].w;
        }
        __syncwarp();

        // ---- consume: 8x (LDS.128 + STG.128), full-line stores ----
#pragma unroll
        for (int k = 0; k < 8; k++) {
            const int chh  = 4 * k + d;                       // 0..31
            const int addr = chh * 32 + ((c8 * 4) ^ (8 * (k & 3)));
            float4 v = *reinterpret_cast<const float4*>(buf + addr);
            *reinterpret_cast<float4*>(
                outb + (size_t)(32 * h + chh) * HW + c8 * 4) = v;
        }
        __syncwarp();   // protect buf before next half overwrites it
    }
}

extern "C" void kernel_launch(void* const* d_in, const int* in_sizes, int n_in,
                              void* d_out, int out_size) {
    const float* feats  = (const float*)d_in[0];   // (P, 64) float32
    const int*   coords = (const int*)d_in[1];     // (P, 3) int32
    float*       out    = (float*)d_out;           // (B, 64, 512, 512) float32

    int P = in_sizes[0] / BEV_C;
    int B = out_size / (BEV_C * HW);
    if (B > 8) B = 8;
    int ncells = B * HW;

    // 1) init last-index grid to -1 (memset node; 0xFF bytes == -1 int)
    void* lastPtr = nullptr;
    cudaGetSymbolAddress(&lastPtr, g_last);
    cudaMemsetAsync(lastPtr, 0xFF, (size_t)ncells * sizeof(int), 0);

    // 2) scatter
    int nt = (P + 3) / 4;
    bev_scatter_kernel<<<(nt + 255) / 256, 256>>>(coords, P);

    // 3) gather + transpose: 32 cells per warp, 8 warps per CTA
    bev_gather_kernel<<<ncells / 256, 256>>>(feats, out);
}